// round 1
// baseline (speedup 1.0000x reference)
#include <cuda_runtime.h>
#include <math.h>

#define D_MODEL 1024
#define NH 16
#define DH 64
#define BATCH 4
#define SEQ 1024
#define MROWS (BATCH*SEQ)        // 4096
#define QK_COUNT 4194304.0f      // 4*1024*16*64 elements in q (and k)
#define EPS 1e-6f

// ---------------- scratch (device globals; no allocation allowed) ----------
__device__ float g_qkv[MROWS * 3 * D_MODEL];   // 48 MB
__device__ float g_z[MROWS * D_MODEL];         // 16 MB
__device__ float g_sumsq[2];
__device__ float g_inv[2];

// ---------------- tiny kernels --------------------------------------------
__global__ void zero2_kernel(float* p) {
    if (threadIdx.x < 2) p[threadIdx.x] = 0.0f;
}

__global__ void finalize_kernel(const float* __restrict__ ss, float* __restrict__ inv) {
    if (threadIdx.x < 2) {
        float rms = sqrtf(ss[threadIdx.x] / QK_COUNT);
        inv[threadIdx.x] = 1.0f / (rms + EPS);
    }
}

// ---------------- SGEMM: C[M,N] = A[M,K] @ B[K,N] --------------------------
// 128x128 block, BK=16, 256 threads, 8x8 per-thread microtile.
// do_sumsq: for the QKV GEMM, accumulate sum of squares of C for column
// regions [0,1024) -> sumsq[0] (q) and [1024,2048) -> sumsq[1] (k).
__global__ __launch_bounds__(256)
void sgemm_kernel(const float* __restrict__ A, const float* __restrict__ B,
                  float* __restrict__ C, int M, int N, int K,
                  float* sumsq, int do_sumsq)
{
    __shared__ float As[16][128];   // [k][m]
    __shared__ float Bs[16][128];   // [k][n]
    __shared__ float red[256];

    const int tid  = threadIdx.x;
    const int bcol = blockIdx.x;
    const int brow = blockIdx.y;
    const int trow = (tid >> 4) * 8;   // 0..120
    const int tcol = (tid & 15) * 8;   // 0..120

    const float* Ab = A + (size_t)brow * 128 * K;
    const float* Bb = B + (size_t)bcol * 128;

    float acc[8][8];
#pragma unroll
    for (int i = 0; i < 8; i++)
#pragma unroll
        for (int j = 0; j < 8; j++) acc[i][j] = 0.0f;

    for (int k0 = 0; k0 < K; k0 += 16) {
        // load A tile 128x16 (transposed into As[k][m])
#pragma unroll
        for (int l = 0; l < 2; l++) {
            int idx = tid + l * 256;            // 0..511
            int ar  = idx >> 2;                 // 0..127
            int ak  = (idx & 3) * 4;            // 0,4,8,12
            float4 v = *(const float4*)(Ab + (size_t)ar * K + k0 + ak);
            As[ak + 0][ar] = v.x;
            As[ak + 1][ar] = v.y;
            As[ak + 2][ar] = v.z;
            As[ak + 3][ar] = v.w;
        }
        // load B tile 16x128
#pragma unroll
        for (int l = 0; l < 2; l++) {
            int idx = tid + l * 256;
            int br  = idx >> 5;                 // 0..15
            int bc  = (idx & 31) * 4;           // 0..124
            *(float4*)(&Bs[br][bc]) = *(const float4*)(Bb + (size_t)(k0 + br) * N + bc);
        }
        __syncthreads();

#pragma unroll
        for (int kk = 0; kk < 16; kk++) {
            float4 a0 = *(const float4*)&As[kk][trow];
            float4 a1 = *(const float4*)&As[kk][trow + 4];
            float4 b0 = *(const float4*)&Bs[kk][tcol];
            float4 b1 = *(const float4*)&Bs[kk][tcol + 4];
            float av[8] = {a0.x, a0.y, a0.z, a0.w, a1.x, a1.y, a1.z, a1.w};
            float bv[8] = {b0.x, b0.y, b0.z, b0.w, b1.x, b1.y, b1.z, b1.w};
#pragma unroll
            for (int i = 0; i < 8; i++)
#pragma unroll
                for (int j = 0; j < 8; j++)
                    acc[i][j] = fmaf(av[i], bv[j], acc[i][j]);
        }
        __syncthreads();
    }

    // store C
    float* Cb = C + (size_t)brow * 128 * N + (size_t)bcol * 128;
#pragma unroll
    for (int i = 0; i < 8; i++) {
        float4 c0 = {acc[i][0], acc[i][1], acc[i][2], acc[i][3]};
        float4 c1 = {acc[i][4], acc[i][5], acc[i][6], acc[i][7]};
        *(float4*)(Cb + (size_t)(trow + i) * N + tcol)     = c0;
        *(float4*)(Cb + (size_t)(trow + i) * N + tcol + 4) = c1;
    }

    if (do_sumsq) {
        int colbase = bcol * 128;
        float ss = 0.0f;
        if (colbase < 2048) {
#pragma unroll
            for (int i = 0; i < 8; i++)
#pragma unroll
                for (int j = 0; j < 8; j++) ss += acc[i][j] * acc[i][j];
        }
        red[tid] = ss;
        __syncthreads();
        for (int s = 128; s > 0; s >>= 1) {
            if (tid < s) red[tid] += red[tid + s];
            __syncthreads();
        }
        if (tid == 0 && colbase < 2048)
            atomicAdd(&sumsq[colbase < 1024 ? 0 : 1], red[0]);
    }
}

// ---------------- Flash attention -----------------------------------------
// One CTA per (q-tile of 128 rows, head, batch). Online softmax over 16
// K/V tiles of 64 rows. RMS normalization + per-dim scales folded into the
// smem loads of Q and K. Output z written to scratch.
//
// smem layout (floats):
//   Qst[64][132]  (d-major, padded)       8448
//   Kst[64][68]   (d-major, padded)       4352
//   Vs [64][68]   (seq-major, padded)     4352
//   Pst[64][132]  (kv-major, padded)      8448
// total 25600 floats = 102400 bytes
__global__ __launch_bounds__(256)
void flash_kernel(const float* __restrict__ qkv, const float* __restrict__ inv,
                  const float* __restrict__ scale_q, const float* __restrict__ scale_k,
                  float* __restrict__ z)
{
    extern __shared__ float sm[];
    float* Qst = sm;                    // [d][r]  stride 132
    float* Kst = Qst + 64 * 132;        // [d][c]  stride 68
    float* Vs  = Kst + 64 * 68;         // [j][c]  stride 68
    float* Pst = Vs  + 64 * 68;         // [j][r]  stride 132

    const int tid = threadIdx.x;
    const int qt  = blockIdx.x;   // 0..7
    const int h   = blockIdx.y;   // 0..15
    const int b   = blockIdx.z;   // 0..3
    const int trow = (tid >> 4) * 8;    // 0..120
    const int tcol = (tid & 15) * 4;    // 0..60

    const float invq = inv[0];
    const float invk = inv[1];

    // ---- load Q tile (128 x 64), scaled, stored d-major ----
    {
        const int base = b * SEQ + qt * 128;
#pragma unroll
        for (int l = 0; l < 8; l++) {
            int idx = tid + l * 256;
            int r   = idx >> 4;            // 0..127
            int d4  = idx & 15;
            int d   = d4 * 4;
            float4 v = *(const float4*)(qkv + (size_t)(base + r) * 3072 + h * DH + d);
            Qst[(d + 0) * 132 + r] = v.x * invq * scale_q[d + 0];
            Qst[(d + 1) * 132 + r] = v.y * invq * scale_q[d + 1];
            Qst[(d + 2) * 132 + r] = v.z * invq * scale_q[d + 2];
            Qst[(d + 3) * 132 + r] = v.w * invq * scale_q[d + 3];
        }
    }

    float o[8][4];
    float mrow[8], lrow[8];
#pragma unroll
    for (int i = 0; i < 8; i++) {
        mrow[i] = -INFINITY; lrow[i] = 0.0f;
#pragma unroll
        for (int j = 0; j < 4; j++) o[i][j] = 0.0f;
    }

    for (int t = 0; t < 16; t++) {
        __syncthreads();   // previous tile's GEMM2 done reading Pst/Vs

        // ---- load K tile (scaled, d-major) and V tile (seq-major) ----
#pragma unroll
        for (int u = 0; u < 4; u++) {
            int idx = tid + u * 256;
            int c   = idx >> 4;            // kv row in tile 0..63
            int d4  = idx & 15;
            int d   = d4 * 4;
            int srow = b * SEQ + t * 64 + c;
            float4 kv = *(const float4*)(qkv + (size_t)srow * 3072 + 1024 + h * DH + d);
            Kst[(d + 0) * 68 + c] = kv.x * invk * scale_k[d + 0];
            Kst[(d + 1) * 68 + c] = kv.y * invk * scale_k[d + 1];
            Kst[(d + 2) * 68 + c] = kv.z * invk * scale_k[d + 2];
            Kst[(d + 3) * 68 + c] = kv.w * invk * scale_k[d + 3];
            float4 vv = *(const float4*)(qkv + (size_t)srow * 3072 + 2048 + h * DH + d);
            *(float4*)&Vs[c * 68 + d] = vv;
        }
        __syncthreads();

        // ---- S = Q' @ K'^T  (128 x 64 tile) ----
        float sreg[8][4];
#pragma unroll
        for (int i = 0; i < 8; i++)
#pragma unroll
            for (int j = 0; j < 4; j++) sreg[i][j] = 0.0f;

#pragma unroll 8
        for (int d = 0; d < 64; d++) {
            float4 a0 = *(const float4*)&Qst[d * 132 + trow];
            float4 a1 = *(const float4*)&Qst[d * 132 + trow + 4];
            float4 bb = *(const float4*)&Kst[d * 68 + tcol];
            float av[8] = {a0.x, a0.y, a0.z, a0.w, a1.x, a1.y, a1.z, a1.w};
            float bv[4] = {bb.x, bb.y, bb.z, bb.w};
#pragma unroll
            for (int i = 0; i < 8; i++)
#pragma unroll
                for (int j = 0; j < 4; j++)
                    sreg[i][j] = fmaf(av[i], bv[j], sreg[i][j]);
        }

        // ---- online softmax update; write P (kv-major) ----
#pragma unroll
        for (int i = 0; i < 8; i++) {
            float tmax = fmaxf(fmaxf(sreg[i][0], sreg[i][1]), fmaxf(sreg[i][2], sreg[i][3]));
#pragma unroll
            for (int off = 8; off >= 1; off >>= 1)
                tmax = fmaxf(tmax, __shfl_xor_sync(0xffffffffu, tmax, off));
            float mnew = fmaxf(mrow[i], tmax);
            float corr = __expf(mrow[i] - mnew);   // 0 on first tile (-inf)
            float psum = 0.0f;
#pragma unroll
            for (int j = 0; j < 4; j++) {
                float p = __expf(sreg[i][j] - mnew);
                psum += p;
                Pst[(tcol + j) * 132 + (trow + i)] = p;
            }
#pragma unroll
            for (int off = 8; off >= 1; off >>= 1)
                psum += __shfl_xor_sync(0xffffffffu, psum, off);
            lrow[i] = lrow[i] * corr + psum;
            mrow[i] = mnew;
#pragma unroll
            for (int j = 0; j < 4; j++) o[i][j] *= corr;
        }
        __syncthreads();

        // ---- O += P @ V ----
#pragma unroll 8
        for (int j = 0; j < 64; j++) {
            float4 p0 = *(const float4*)&Pst[j * 132 + trow];
            float4 p1 = *(const float4*)&Pst[j * 132 + trow + 4];
            float4 vv = *(const float4*)&Vs[j * 68 + tcol];
            float pv[8] = {p0.x, p0.y, p0.z, p0.w, p1.x, p1.y, p1.z, p1.w};
            float vvv[4] = {vv.x, vv.y, vv.z, vv.w};
#pragma unroll
            for (int i = 0; i < 8; i++)
#pragma unroll
                for (int c = 0; c < 4; c++)
                    o[i][c] = fmaf(pv[i], vvv[c], o[i][c]);
        }
    }

    // ---- epilogue: z = O / l ----
#pragma unroll
    for (int i = 0; i < 8; i++) {
        float rl = 1.0f / lrow[i];
        float4 out = {o[i][0] * rl, o[i][1] * rl, o[i][2] * rl, o[i][3] * rl};
        int row = b * SEQ + qt * 128 + trow + i;
        *(float4*)(z + (size_t)row * D_MODEL + h * DH + tcol) = out;
    }
}

// ---------------- launcher --------------------------------------------------
extern "C" void kernel_launch(void* const* d_in, const int* in_sizes, int n_in,
                              void* d_out, int out_size)
{
    const float* x    = (const float*)d_in[0];
    const float* Wqkv = (const float*)d_in[1];
    const float* Wo   = (const float*)d_in[2];
    const float* sq   = (const float*)d_in[3];
    const float* sk   = (const float*)d_in[4];
    float* out = (float*)d_out;

    float *qkv, *z, *ss, *inv;
    cudaGetSymbolAddress((void**)&qkv, g_qkv);
    cudaGetSymbolAddress((void**)&z,   g_z);
    cudaGetSymbolAddress((void**)&ss,  g_sumsq);
    cudaGetSymbolAddress((void**)&inv, g_inv);

    // 1) zero sumsq accumulators
    zero2_kernel<<<1, 32>>>(ss);

    // 2) QKV GEMM with fused q/k sum-of-squares
    sgemm_kernel<<<dim3(3 * D_MODEL / 128, MROWS / 128), 256>>>(
        x, Wqkv, qkv, MROWS, 3 * D_MODEL, D_MODEL, ss, 1);

    // 3) finalize 1/(rms+eps)
    finalize_kernel<<<1, 32>>>(ss, inv);

    // 4) flash attention
    cudaFuncSetAttribute(flash_kernel, cudaFuncAttributeMaxDynamicSharedMemorySize, 102400);
    flash_kernel<<<dim3(SEQ / 128, NH, BATCH), 256, 102400>>>(qkv, inv, sq, sk, z);

    // 5) output GEMM
    sgemm_kernel<<<dim3(D_MODEL / 128, MROWS / 128), 256>>>(
        z, Wo, out, MROWS, D_MODEL, D_MODEL, nullptr, 0);
}